// round 1
// baseline (speedup 1.0000x reference)
#include <cuda_runtime.h>

#define NMAX 200000
#define EMAX 6400000
#define DIM 16

// ---------------- static device scratch (no allocation allowed) ----------------
static __device__ int   g_src[EMAX];
static __device__ int   g_dst[EMAX];
static __device__ int   g_rank[EMAX];
static __device__ int   g_csr_src[EMAX];
static __device__ float g_csr_coef[EMAX];
static __device__ int   g_cnt[NMAX];
static __device__ int   g_excl[NMAX];
static __device__ int   g_rowstart[NMAX + 1];
static __device__ int   g_bsums[1024];
static __device__ int   g_boffs[1024];
static __device__ float g_dinv[NMAX];
static __device__ float g_h[NMAX * DIM];   // current node features
static __device__ float g_a[NMAX * DIM];   // aggregation output
static __device__ float g_y[NMAX * DIM];   // matmul output (pre-BN)
static __device__ float g_stats[2 * DIM];  // [sum(16), sumsq(16)]
static __device__ float g_ss[2 * DIM];     // [scale(16), shift(16)]
static __device__ int   g_is64;

// ---------------- setup kernels ----------------

__global__ void k_zero_cnt(int n) {
    int i = blockIdx.x * blockDim.x + threadIdx.x;
    if (i < n) g_cnt[i] = 0;
}

// Detect whether edge_index is int64 (high words all zero) or int32.
__global__ void k_detect(const int* __restrict__ ei, int npairs) {
    __shared__ int any;
    if (threadIdx.x == 0) any = 0;
    __syncthreads();
    for (int i = threadIdx.x; i < npairs; i += blockDim.x) {
        if (ei[2 * i + 1] != 0) atomicOr(&any, 1);
    }
    __syncthreads();
    if (threadIdx.x == 0) g_is64 = (any == 0) ? 1 : 0;
}

// Decode edge_index, histogram in-degree, record per-edge rank within dst bucket.
__global__ void k_convert(const int* __restrict__ ei, int E) {
    int e = blockIdx.x * blockDim.x + threadIdx.x;
    if (e >= E) return;
    int s, d;
    if (g_is64) { s = ei[2 * e]; d = ei[2 * E + 2 * e]; }
    else        { s = ei[e];     d = ei[E + e]; }
    g_src[e] = s;
    g_dst[e] = d;
    g_rank[e] = atomicAdd(&g_cnt[d], 1);
}

__global__ void k_dinv(int n) {
    int i = blockIdx.x * blockDim.x + threadIdx.x;
    if (i < n) g_dinv[i] = rsqrtf((float)g_cnt[i] + 1.0f);  // +1 self loop
}

// ---------------- exclusive scan of g_cnt -> g_rowstart ----------------
// 1024 elements per block (256 threads x 4)

__global__ void k_scan_block(int n) {
    __shared__ int sh[256];
    int tid = threadIdx.x;
    int base = blockIdx.x * 1024 + tid * 4;
    int v0 = 0, v1 = 0, v2 = 0, v3 = 0;
    if (base + 0 < n) v0 = g_cnt[base + 0];
    if (base + 1 < n) v1 = g_cnt[base + 1];
    if (base + 2 < n) v2 = g_cnt[base + 2];
    if (base + 3 < n) v3 = g_cnt[base + 3];
    int tsum = v0 + v1 + v2 + v3;
    sh[tid] = tsum;
    __syncthreads();
    for (int off = 1; off < 256; off <<= 1) {
        int t = 0;
        if (tid >= off) t = sh[tid - off];
        __syncthreads();
        sh[tid] += t;
        __syncthreads();
    }
    int excl = sh[tid] - tsum;
    if (base + 0 < n) { g_excl[base + 0] = excl; excl += v0; }
    if (base + 1 < n) { g_excl[base + 1] = excl; excl += v1; }
    if (base + 2 < n) { g_excl[base + 2] = excl; excl += v2; }
    if (base + 3 < n) { g_excl[base + 3] = excl; }
    if (tid == 255) g_bsums[blockIdx.x] = sh[255];
}

__global__ void k_scan_top(int nb) {
    __shared__ int sh[256];
    int tid = threadIdx.x;
    int v = (tid < nb) ? g_bsums[tid] : 0;
    sh[tid] = v;
    __syncthreads();
    for (int off = 1; off < 256; off <<= 1) {
        int t = 0;
        if (tid >= off) t = sh[tid - off];
        __syncthreads();
        sh[tid] += t;
        __syncthreads();
    }
    g_boffs[tid] = sh[tid] - v;  // exclusive
}

__global__ void k_scan_final(int n, int E) {
    int i = blockIdx.x * blockDim.x + threadIdx.x;
    if (i < n) g_rowstart[i] = g_excl[i] + g_boffs[i >> 10];
    if (i == 0) g_rowstart[n] = E;
}

// Fill CSR: pos = rowstart[dst] + rank (no atomics).
__global__ void k_fill(int E) {
    int e = blockIdx.x * blockDim.x + threadIdx.x;
    if (e >= E) return;
    int s = g_src[e];
    int d = g_dst[e];
    int pos = g_rowstart[d] + g_rank[e];
    g_csr_src[pos] = s;
    g_csr_coef[pos] = g_dinv[s] * g_dinv[d];
}

// ---------------- dense kernels ----------------

// g_h = x[n,64] @ W[64,16]
__global__ void k_xw(const float* __restrict__ x, const float* __restrict__ W, int n) {
    __shared__ float sW[64 * 16];
    int tid = threadIdx.x;
    ((float4*)sW)[tid] = ((const float4*)W)[tid];  // 256 float4 = 1024 floats
    __syncthreads();
    int row = blockIdx.x * 256 + tid;
    if (row >= n) return;
    const float4* xr = (const float4*)(x + (size_t)row * 64);
    float y[16];
#pragma unroll
    for (int j = 0; j < 16; j++) y[j] = 0.0f;
#pragma unroll
    for (int k4 = 0; k4 < 16; k4++) {
        float4 xv = xr[k4];
        int kb = k4 * 4;
#pragma unroll
        for (int j = 0; j < 16; j++) y[j] += xv.x * sW[(kb + 0) * 16 + j];
#pragma unroll
        for (int j = 0; j < 16; j++) y[j] += xv.y * sW[(kb + 1) * 16 + j];
#pragma unroll
        for (int j = 0; j < 16; j++) y[j] += xv.z * sW[(kb + 2) * 16 + j];
#pragma unroll
        for (int j = 0; j < 16; j++) y[j] += xv.w * sW[(kb + 3) * 16 + j];
    }
    float4* o = (float4*)(g_h + (size_t)row * 16);
    o[0] = make_float4(y[0], y[1], y[2], y[3]);
    o[1] = make_float4(y[4], y[5], y[6], y[7]);
    o[2] = make_float4(y[8], y[9], y[10], y[11]);
    o[3] = make_float4(y[12], y[13], y[14], y[15]);
}

// g_a = D^{-1/2}(A+I)D^{-1/2} g_h   (CSR gather, 4 threads per node, float4 each)
__global__ void k_agg(int n) {
    int idx = blockIdx.x * blockDim.x + threadIdx.x;
    if (idx >= n * 4) return;
    int i = idx >> 2, q = idx & 3;
    const float4* H4 = (const float4*)g_h;
    float di = g_dinv[i];
    float c0 = di * di;
    float4 acc = H4[(size_t)i * 4 + q];
    acc.x *= c0; acc.y *= c0; acc.z *= c0; acc.w *= c0;
    int e = g_rowstart[i], e1 = g_rowstart[i + 1];
    for (; e + 4 <= e1; e += 4) {
        int s0 = g_csr_src[e + 0], s1 = g_csr_src[e + 1];
        int s2 = g_csr_src[e + 2], s3 = g_csr_src[e + 3];
        float ca = g_csr_coef[e + 0], cb = g_csr_coef[e + 1];
        float cc = g_csr_coef[e + 2], cd = g_csr_coef[e + 3];
        float4 v0 = H4[(size_t)s0 * 4 + q];
        float4 v1 = H4[(size_t)s1 * 4 + q];
        float4 v2 = H4[(size_t)s2 * 4 + q];
        float4 v3 = H4[(size_t)s3 * 4 + q];
        acc.x += ca * v0.x; acc.y += ca * v0.y; acc.z += ca * v0.z; acc.w += ca * v0.w;
        acc.x += cb * v1.x; acc.y += cb * v1.y; acc.z += cb * v1.z; acc.w += cb * v1.w;
        acc.x += cc * v2.x; acc.y += cc * v2.y; acc.z += cc * v2.z; acc.w += cc * v2.w;
        acc.x += cd * v3.x; acc.y += cd * v3.y; acc.z += cd * v3.z; acc.w += cd * v3.w;
    }
    for (; e < e1; e++) {
        int s = g_csr_src[e];
        float c = g_csr_coef[e];
        float4 v = H4[(size_t)s * 4 + q];
        acc.x += c * v.x; acc.y += c * v.y; acc.z += c * v.z; acc.w += c * v.w;
    }
    ((float4*)g_a)[(size_t)i * 4 + q] = acc;
}

// g_h = g_a + b (broadcast)
__global__ void k_bias(const float* __restrict__ b, int n4) {
    int idx = blockIdx.x * blockDim.x + threadIdx.x;
    if (idx >= n4) return;
    float4 v = ((const float4*)g_a)[idx];
    float4 bb = ((const float4*)b)[idx & 3];
    v.x += bb.x; v.y += bb.y; v.z += bb.z; v.w += bb.w;
    ((float4*)g_h)[idx] = v;
}

__global__ void k_zero_stats() {
    if (threadIdx.x < 32) g_stats[threadIdx.x] = 0.0f;
}

// g_y = g_a @ W[16,16] + b; accumulate per-channel sum & sumsq into g_stats
__global__ void k_mm_stats(const float* __restrict__ W, const float* __restrict__ b, int n) {
    __shared__ float sW[256];
    __shared__ float sB[16];
    __shared__ float sSum[16], sSq[16];
    int tid = threadIdx.x;
    sW[tid] = W[tid];
    if (tid < 16) { sB[tid] = b[tid]; sSum[tid] = 0.0f; sSq[tid] = 0.0f; }
    __syncthreads();
    int row = blockIdx.x * 256 + tid;
    float y[16];
    if (row < n) {
        const float4* A4 = (const float4*)(g_a + (size_t)row * 16);
        float a[16];
        float4 t;
        t = A4[0]; a[0] = t.x; a[1] = t.y; a[2] = t.z; a[3] = t.w;
        t = A4[1]; a[4] = t.x; a[5] = t.y; a[6] = t.z; a[7] = t.w;
        t = A4[2]; a[8] = t.x; a[9] = t.y; a[10] = t.z; a[11] = t.w;
        t = A4[3]; a[12] = t.x; a[13] = t.y; a[14] = t.z; a[15] = t.w;
#pragma unroll
        for (int j = 0; j < 16; j++) y[j] = sB[j];
#pragma unroll
        for (int k = 0; k < 16; k++) {
            float av = a[k];
#pragma unroll
            for (int j = 0; j < 16; j++) y[j] += av * sW[k * 16 + j];
        }
        float4* O = (float4*)(g_y + (size_t)row * 16);
        O[0] = make_float4(y[0], y[1], y[2], y[3]);
        O[1] = make_float4(y[4], y[5], y[6], y[7]);
        O[2] = make_float4(y[8], y[9], y[10], y[11]);
        O[3] = make_float4(y[12], y[13], y[14], y[15]);
    } else {
#pragma unroll
        for (int j = 0; j < 16; j++) y[j] = 0.0f;
    }
    // warp reduction per channel
#pragma unroll
    for (int j = 0; j < 16; j++) {
        float s = y[j];
        float q = y[j] * y[j];
#pragma unroll
        for (int off = 16; off > 0; off >>= 1) {
            s += __shfl_xor_sync(0xFFFFFFFFu, s, off);
            q += __shfl_xor_sync(0xFFFFFFFFu, q, off);
        }
        if ((tid & 31) == 0) {
            atomicAdd(&sSum[j], s);
            atomicAdd(&sSq[j], q);
        }
    }
    __syncthreads();
    if (tid < 16) {
        atomicAdd(&g_stats[tid], sSum[tid]);
        atomicAdd(&g_stats[16 + tid], sSq[tid]);
    }
}

__global__ void k_scale_shift(const float* __restrict__ gamma, const float* __restrict__ beta, float fn) {
    int j = threadIdx.x;
    if (j >= 16) return;
    float m = g_stats[j] / fn;
    float v = g_stats[16 + j] / fn - m * m;
    v = fmaxf(v, 0.0f);
    float sc = gamma[j] * rsqrtf(v + 1e-5f);
    g_ss[j] = sc;
    g_ss[16 + j] = beta[j] - m * sc;
}

// g_h = relu(g_y * scale + shift)
__global__ void k_bn_relu(int n4) {
    int idx = blockIdx.x * blockDim.x + threadIdx.x;
    if (idx >= n4) return;
    int q = idx & 3;
    float4 sc = ((const float4*)g_ss)[q];
    float4 sh = ((const float4*)(g_ss + 16))[q];
    float4 v = ((const float4*)g_y)[idx];
    v.x = fmaxf(v.x * sc.x + sh.x, 0.0f);
    v.y = fmaxf(v.y * sc.y + sh.y, 0.0f);
    v.z = fmaxf(v.z * sc.z + sh.z, 0.0f);
    v.w = fmaxf(v.w * sc.w + sh.w, 0.0f);
    ((float4*)g_h)[idx] = v;
}

// sin_out / cos_out heads from shared aggregation g_a
__global__ void k_final(const float* __restrict__ Wsin, const float* __restrict__ bsin,
                        const float* __restrict__ Wcos, const float* __restrict__ bcos,
                        float* __restrict__ out, int n) {
    __shared__ float sWs[256], sWc[256];
    __shared__ float sBs[16], sBc[16];
    int tid = threadIdx.x;
    sWs[tid] = Wsin[tid];
    sWc[tid] = Wcos[tid];
    if (tid < 16) { sBs[tid] = bsin[tid]; sBc[tid] = bcos[tid]; }
    __syncthreads();
    int row = blockIdx.x * 256 + tid;
    if (row >= n) return;
    const float4* A4 = (const float4*)(g_a + (size_t)row * 16);
    float a[16];
    float4 t;
    t = A4[0]; a[0] = t.x; a[1] = t.y; a[2] = t.z; a[3] = t.w;
    t = A4[1]; a[4] = t.x; a[5] = t.y; a[6] = t.z; a[7] = t.w;
    t = A4[2]; a[8] = t.x; a[9] = t.y; a[10] = t.z; a[11] = t.w;
    t = A4[3]; a[12] = t.x; a[13] = t.y; a[14] = t.z; a[15] = t.w;
    float ys[16], yc[16];
#pragma unroll
    for (int j = 0; j < 16; j++) { ys[j] = sBs[j]; yc[j] = sBc[j]; }
#pragma unroll
    for (int k = 0; k < 16; k++) {
        float av = a[k];
#pragma unroll
        for (int j = 0; j < 16; j++) {
            ys[j] += av * sWs[k * 16 + j];
            yc[j] += av * sWc[k * 16 + j];
        }
    }
#pragma unroll
    for (int j = 0; j < 16; j++) {
        ys[j] = fmaxf(ys[j], 0.0f);
        yc[j] = fmaxf(yc[j], 0.0f);
    }
    float4* Os = (float4*)(out + (size_t)row * 16);
    float4* Oc = (float4*)(out + (size_t)n * 16 + (size_t)row * 16);
    Os[0] = make_float4(ys[0], ys[1], ys[2], ys[3]);
    Os[1] = make_float4(ys[4], ys[5], ys[6], ys[7]);
    Os[2] = make_float4(ys[8], ys[9], ys[10], ys[11]);
    Os[3] = make_float4(ys[12], ys[13], ys[14], ys[15]);
    Oc[0] = make_float4(yc[0], yc[1], yc[2], yc[3]);
    Oc[1] = make_float4(yc[4], yc[5], yc[6], yc[7]);
    Oc[2] = make_float4(yc[8], yc[9], yc[10], yc[11]);
    Oc[3] = make_float4(yc[12], yc[13], yc[14], yc[15]);
}

// ---------------- host launcher ----------------

extern "C" void kernel_launch(void* const* d_in, const int* in_sizes, int n_in,
                              void* d_out, int out_size) {
    const float* x      = (const float*)d_in[0];
    const int*   ei     = (const int*)d_in[1];
    const float* W_in   = (const float*)d_in[2];
    const float* b_in   = (const float*)d_in[3];
    const float* Ws     = (const float*)d_in[4];
    const float* bs     = (const float*)d_in[5];
    const float* gammas = (const float*)d_in[6];
    const float* betas  = (const float*)d_in[7];
    const float* W_sin  = (const float*)d_in[8];
    const float* b_sin  = (const float*)d_in[9];
    const float* W_cos  = (const float*)d_in[10];
    const float* b_cos  = (const float*)d_in[11];
    float* out = (float*)d_out;

    int n = in_sizes[0] / 64;
    int E = in_sizes[1] / 2;
    int n4 = n * 4;

    int nbn  = (n + 255) / 256;
    int nbn4 = (n4 + 255) / 256;
    int nbe  = (E + 255) / 256;
    int nsb  = (n + 1023) / 1024;

    // ---- graph preprocessing (per call; deterministic) ----
    k_zero_cnt<<<nbn, 256>>>(n);
    k_detect<<<1, 256>>>(ei, (E < 1024) ? E : 1024);
    k_convert<<<nbe, 256>>>(ei, E);
    k_dinv<<<nbn, 256>>>(n);
    k_scan_block<<<nsb, 256>>>(n);
    k_scan_top<<<1, 256>>>(nsb);
    k_scan_final<<<nbn, 256>>>(n, E);
    k_fill<<<nbe, 256>>>(E);

    // ---- input layer: h = agg(x @ W_in) + b_in ----
    k_xw<<<nbn, 256>>>(x, W_in, n);
    k_agg<<<nbn4, 256>>>(n);
    k_bias<<<nbn4, 256>>>(b_in, n4);

    // ---- 4 mid layers: h = relu(BN(agg(h) @ Ws[l] + bs[l])) ----
    for (int l = 0; l < 4; l++) {
        k_agg<<<nbn4, 256>>>(n);
        k_zero_stats<<<1, 32>>>();
        k_mm_stats<<<nbn, 256>>>(Ws + l * 256, bs + l * 16, n);
        k_scale_shift<<<1, 16>>>(gammas + l * 16, betas + l * 16, (float)n);
        k_bn_relu<<<nbn4, 256>>>(n4);
    }

    // ---- output heads share one aggregation ----
    k_agg<<<nbn4, 256>>>(n);
    k_final<<<nbn, 256>>>(W_sin, b_sin, W_cos, b_cos, out, n);
}

// round 2
// speedup vs baseline: 1.8134x; 1.8134x over previous
#include <cuda_runtime.h>
#include <cuda_fp16.h>

#define NMAX 200000
#define EMAX 6400000

// ---------------- static device scratch ----------------
static __device__ int2  g_csr[EMAX];           // {src, coef_bits}
static __device__ int   g_cnt[NMAX];
static __device__ int   g_cursor[NMAX];
static __device__ int   g_excl[NMAX];
static __device__ int   g_rowstart[NMAX + 1];
static __device__ int   g_bsums[1024];
static __device__ int   g_boffs[1024];
static __device__ float g_dinv[NMAX];
static __device__ uint2 g_hA[NMAX * 4];        // fp16x4 per quarter-row
static __device__ uint2 g_hB[NMAX * 4];
static __device__ float g_a[NMAX * 16];        // fp32 agg output
static __device__ float g_y[NMAX * 16];        // fp32 pre-BN
static __device__ float g_stats[4 * 32];       // per mid-layer [sum16, sumsq16]
static __device__ int   g_is64;

// ---------------- prep ----------------

// zero cnt; block 0 additionally: detect int64-vs-int32 layout, zero stats
__global__ void k_init(const int* __restrict__ ei, int npairs, int n) {
    int i = blockIdx.x * blockDim.x + threadIdx.x;
    if (i < n) g_cnt[i] = 0;
    if (blockIdx.x == 0) {
        __shared__ int any;
        if (threadIdx.x == 0) any = 0;
        __syncthreads();
        for (int k = threadIdx.x; k < npairs; k += blockDim.x)
            if (ei[2 * k + 1] != 0) atomicOr(&any, 1);
        __syncthreads();
        if (threadIdx.x == 0) g_is64 = (any == 0) ? 1 : 0;
        if (threadIdx.x < 128) g_stats[threadIdx.x] = 0.0f;
    }
}

__global__ void k_count(const int* __restrict__ ei, int E) {
    int e = blockIdx.x * blockDim.x + threadIdx.x;
    if (e >= E) return;
    int d = g_is64 ? ei[2 * E + 2 * e] : ei[E + e];
    atomicAdd(&g_cnt[d], 1);
}

// exclusive scan of g_cnt (1024 elems/block)
__global__ void k_scan_block(int n) {
    __shared__ int sh[256];
    int tid = threadIdx.x;
    int base = blockIdx.x * 1024 + tid * 4;
    int v0 = 0, v1 = 0, v2 = 0, v3 = 0;
    if (base + 0 < n) v0 = g_cnt[base + 0];
    if (base + 1 < n) v1 = g_cnt[base + 1];
    if (base + 2 < n) v2 = g_cnt[base + 2];
    if (base + 3 < n) v3 = g_cnt[base + 3];
    int tsum = v0 + v1 + v2 + v3;
    sh[tid] = tsum;
    __syncthreads();
    for (int off = 1; off < 256; off <<= 1) {
        int t = 0;
        if (tid >= off) t = sh[tid - off];
        __syncthreads();
        sh[tid] += t;
        __syncthreads();
    }
    int excl = sh[tid] - tsum;
    if (base + 0 < n) { g_excl[base + 0] = excl; excl += v0; }
    if (base + 1 < n) { g_excl[base + 1] = excl; excl += v1; }
    if (base + 2 < n) { g_excl[base + 2] = excl; excl += v2; }
    if (base + 3 < n) { g_excl[base + 3] = excl; }
    if (tid == 255) g_bsums[blockIdx.x] = sh[255];
}

__global__ void k_scan_top(int nb) {
    __shared__ int sh[256];
    int tid = threadIdx.x;
    int v = (tid < nb) ? g_bsums[tid] : 0;
    sh[tid] = v;
    __syncthreads();
    for (int off = 1; off < 256; off <<= 1) {
        int t = 0;
        if (tid >= off) t = sh[tid - off];
        __syncthreads();
        sh[tid] += t;
        __syncthreads();
    }
    g_boffs[tid] = sh[tid] - v;
}

__global__ void k_scan_final(int n, int E) {
    int i = blockIdx.x * blockDim.x + threadIdx.x;
    if (i < n) {
        int rs = g_excl[i] + g_boffs[i >> 10];
        g_rowstart[i] = rs;
        g_cursor[i] = rs;
        g_dinv[i] = rsqrtf((float)g_cnt[i] + 1.0f);  // +1 self loop
    }
    if (i == 0) g_rowstart[n] = E;
}

__global__ void k_fill(const int* __restrict__ ei, int E) {
    int e = blockIdx.x * blockDim.x + threadIdx.x;
    if (e >= E) return;
    int s, d;
    if (g_is64) { s = ei[2 * e]; d = ei[2 * E + 2 * e]; }
    else        { s = ei[e];     d = ei[E + e]; }
    float c = g_dinv[s] * g_dinv[d];
    int pos = atomicAdd(&g_cursor[d], 1);
    g_csr[pos] = make_int2(s, __float_as_int(c));
}

// ---------------- dense ----------------

// g_hA = fp16(x[n,64] @ W[64,16])
__global__ void k_xw(const float* __restrict__ x, const float* __restrict__ W, int n) {
    __shared__ float sW[64 * 16];
    int tid = threadIdx.x;
    ((float4*)sW)[tid] = ((const float4*)W)[tid];
    __syncthreads();
    int row = blockIdx.x * 256 + tid;
    if (row >= n) return;
    const float4* xr = (const float4*)(x + (size_t)row * 64);
    float y[16];
#pragma unroll
    for (int j = 0; j < 16; j++) y[j] = 0.0f;
#pragma unroll
    for (int k4 = 0; k4 < 16; k4++) {
        float4 xv = xr[k4];
        int kb = k4 * 4;
#pragma unroll
        for (int j = 0; j < 16; j++) y[j] += xv.x * sW[(kb + 0) * 16 + j];
#pragma unroll
        for (int j = 0; j < 16; j++) y[j] += xv.y * sW[(kb + 1) * 16 + j];
#pragma unroll
        for (int j = 0; j < 16; j++) y[j] += xv.z * sW[(kb + 2) * 16 + j];
#pragma unroll
        for (int j = 0; j < 16; j++) y[j] += xv.w * sW[(kb + 3) * 16 + j];
    }
    uint2* o = g_hA + (size_t)row * 4;
#pragma unroll
    for (int q = 0; q < 4; q++) {
        __half2 lo = __float22half2_rn(make_float2(y[q * 4 + 0], y[q * 4 + 1]));
        __half2 hi = __float22half2_rn(make_float2(y[q * 4 + 2], y[q * 4 + 3]));
        o[q] = make_uint2(*(unsigned*)&lo, *(unsigned*)&hi);
    }
}

// ---------------- aggregation core ----------------
// 4 lanes per node; lane q owns channels [4q,4q+4). CSR entries shared via
// width-4 shuffles (1 LDG.64 per lane covers 4 edges per group = 8B/edge).
__device__ __forceinline__ float4 agg_core(const uint2* __restrict__ H, int i, int q) {
    float di = g_dinv[i];
    float c0 = di * di;
    uint2 self = H[(size_t)i * 4 + q];
    float2 slo = __half22float2(*(const __half2*)&self.x);
    float2 shi = __half22float2(*(const __half2*)&self.y);
    float4 acc = make_float4(slo.x * c0, slo.y * c0, shi.x * c0, shi.y * c0);
    int lane = threadIdx.x & 31;
    unsigned gmask = 0xFu << (lane & ~3);
    int e = g_rowstart[i], e1 = g_rowstart[i + 1];
    for (; e + 4 <= e1; e += 4) {
        int2 ent = g_csr[e + q];
#pragma unroll
        for (int r = 0; r < 4; r++) {
            int   s = __shfl_sync(gmask, ent.x, r, 4);
            float c = __int_as_float(__shfl_sync(gmask, ent.y, r, 4));
            uint2 v = H[(size_t)s * 4 + q];
            float2 lo = __half22float2(*(const __half2*)&v.x);
            float2 hi = __half22float2(*(const __half2*)&v.y);
            acc.x += c * lo.x; acc.y += c * lo.y;
            acc.z += c * hi.x; acc.w += c * hi.y;
        }
    }
    for (; e < e1; e++) {
        int2 ent = g_csr[e];
        float c = __int_as_float(ent.y);
        uint2 v = H[(size_t)ent.x * 4 + q];
        float2 lo = __half22float2(*(const __half2*)&v.x);
        float2 hi = __half22float2(*(const __half2*)&v.y);
        acc.x += c * lo.x; acc.y += c * lo.y;
        acc.z += c * hi.x; acc.w += c * hi.y;
    }
    return acc;
}

// input layer: hB = fp16(agg(hA) + b_in)
__global__ void k_agg_in(const float* __restrict__ b, int n) {
    int idx = blockIdx.x * blockDim.x + threadIdx.x;
    if (idx >= n * 4) return;
    int i = idx >> 2, q = idx & 3;
    float4 acc = agg_core(g_hA, i, q);
    float4 bb = ((const float4*)b)[q];
    acc.x += bb.x; acc.y += bb.y; acc.z += bb.z; acc.w += bb.w;
    __half2 lo = __float22half2_rn(make_float2(acc.x, acc.y));
    __half2 hi = __float22half2_rn(make_float2(acc.z, acc.w));
    g_hB[(size_t)i * 4 + q] = make_uint2(*(unsigned*)&lo, *(unsigned*)&hi);
}

// mid/head layers: g_a = agg(hB)  (fp32 out)
__global__ void k_agg_mid(int n) {
    int idx = blockIdx.x * blockDim.x + threadIdx.x;
    if (idx >= n * 4) return;
    int i = idx >> 2, q = idx & 3;
    float4 acc = agg_core(g_hB, i, q);
    ((float4*)g_a)[(size_t)i * 4 + q] = acc;
}

// g_y = g_a @ W + b; accumulate per-channel sum & sumsq into g_stats[l]
__global__ void k_mm_stats(const float* __restrict__ W, const float* __restrict__ b,
                           float* __restrict__ stats, int n) {
    __shared__ float sW[256];
    __shared__ float sB[16];
    __shared__ float sSum[16], sSq[16];
    int tid = threadIdx.x;
    sW[tid] = W[tid];
    if (tid < 16) { sB[tid] = b[tid]; sSum[tid] = 0.0f; sSq[tid] = 0.0f; }
    __syncthreads();
    int row = blockIdx.x * 256 + tid;
    float y[16];
    if (row < n) {
        const float4* A4 = (const float4*)(g_a + (size_t)row * 16);
        float a[16];
        float4 t;
        t = A4[0]; a[0] = t.x; a[1] = t.y; a[2] = t.z; a[3] = t.w;
        t = A4[1]; a[4] = t.x; a[5] = t.y; a[6] = t.z; a[7] = t.w;
        t = A4[2]; a[8] = t.x; a[9] = t.y; a[10] = t.z; a[11] = t.w;
        t = A4[3]; a[12] = t.x; a[13] = t.y; a[14] = t.z; a[15] = t.w;
#pragma unroll
        for (int j = 0; j < 16; j++) y[j] = sB[j];
#pragma unroll
        for (int k = 0; k < 16; k++) {
            float av = a[k];
#pragma unroll
            for (int j = 0; j < 16; j++) y[j] += av * sW[k * 16 + j];
        }
        float4* O = (float4*)(g_y + (size_t)row * 16);
        O[0] = make_float4(y[0], y[1], y[2], y[3]);
        O[1] = make_float4(y[4], y[5], y[6], y[7]);
        O[2] = make_float4(y[8], y[9], y[10], y[11]);
        O[3] = make_float4(y[12], y[13], y[14], y[15]);
    } else {
#pragma unroll
        for (int j = 0; j < 16; j++) y[j] = 0.0f;
    }
#pragma unroll
    for (int j = 0; j < 16; j++) {
        float s = y[j];
        float qv = y[j] * y[j];
#pragma unroll
        for (int off = 16; off > 0; off >>= 1) {
            s  += __shfl_xor_sync(0xFFFFFFFFu, s, off);
            qv += __shfl_xor_sync(0xFFFFFFFFu, qv, off);
        }
        if ((tid & 31) == 0) {
            atomicAdd(&sSum[j], s);
            atomicAdd(&sSq[j], qv);
        }
    }
    __syncthreads();
    if (tid < 16) {
        atomicAdd(&stats[tid], sSum[tid]);
        atomicAdd(&stats[16 + tid], sSq[tid]);
    }
}

// hB = fp16(relu(gamma*(y-mean)*rsqrt(var+eps)+beta)); scale/shift computed per block
__global__ void k_bn_relu(const float* __restrict__ stats,
                          const float* __restrict__ gamma, const float* __restrict__ beta,
                          float fn, int n4) {
    __shared__ float sc[16], sh[16];
    int tid = threadIdx.x;
    if (tid < 16) {
        float m = stats[tid] / fn;
        float v = stats[16 + tid] / fn - m * m;
        v = fmaxf(v, 0.0f);
        float s = gamma[tid] * rsqrtf(v + 1e-5f);
        sc[tid] = s;
        sh[tid] = beta[tid] - m * s;
    }
    __syncthreads();
    int idx = blockIdx.x * blockDim.x + tid;
    if (idx >= n4) return;
    int q = idx & 3;
    float4 v = ((const float4*)g_y)[idx];
    v.x = fmaxf(v.x * sc[q * 4 + 0] + sh[q * 4 + 0], 0.0f);
    v.y = fmaxf(v.y * sc[q * 4 + 1] + sh[q * 4 + 1], 0.0f);
    v.z = fmaxf(v.z * sc[q * 4 + 2] + sh[q * 4 + 2], 0.0f);
    v.w = fmaxf(v.w * sc[q * 4 + 3] + sh[q * 4 + 3], 0.0f);
    __half2 lo = __float22half2_rn(make_float2(v.x, v.y));
    __half2 hi = __float22half2_rn(make_float2(v.z, v.w));
    g_hB[idx] = make_uint2(*(unsigned*)&lo, *(unsigned*)&hi);
}

// heads: out = [relu(g_a@Wsin+bsin); relu(g_a@Wcos+bcos)]
__global__ void k_final(const float* __restrict__ Wsin, const float* __restrict__ bsin,
                        const float* __restrict__ Wcos, const float* __restrict__ bcos,
                        float* __restrict__ out, int n) {
    __shared__ float sWs[256], sWc[256];
    __shared__ float sBs[16], sBc[16];
    int tid = threadIdx.x;
    sWs[tid] = Wsin[tid];
    sWc[tid] = Wcos[tid];
    if (tid < 16) { sBs[tid] = bsin[tid]; sBc[tid] = bcos[tid]; }
    __syncthreads();
    int row = blockIdx.x * 256 + tid;
    if (row >= n) return;
    const float4* A4 = (const float4*)(g_a + (size_t)row * 16);
    float a[16];
    float4 t;
    t = A4[0]; a[0] = t.x; a[1] = t.y; a[2] = t.z; a[3] = t.w;
    t = A4[1]; a[4] = t.x; a[5] = t.y; a[6] = t.z; a[7] = t.w;
    t = A4[2]; a[8] = t.x; a[9] = t.y; a[10] = t.z; a[11] = t.w;
    t = A4[3]; a[12] = t.x; a[13] = t.y; a[14] = t.z; a[15] = t.w;
    float ys[16], yc[16];
#pragma unroll
    for (int j = 0; j < 16; j++) { ys[j] = sBs[j]; yc[j] = sBc[j]; }
#pragma unroll
    for (int k = 0; k < 16; k++) {
        float av = a[k];
#pragma unroll
        for (int j = 0; j < 16; j++) {
            ys[j] += av * sWs[k * 16 + j];
            yc[j] += av * sWc[k * 16 + j];
        }
    }
#pragma unroll
    for (int j = 0; j < 16; j++) {
        ys[j] = fmaxf(ys[j], 0.0f);
        yc[j] = fmaxf(yc[j], 0.0f);
    }
    float4* Os = (float4*)(out + (size_t)row * 16);
    float4* Oc = (float4*)(out + (size_t)n * 16 + (size_t)row * 16);
    Os[0] = make_float4(ys[0], ys[1], ys[2], ys[3]);
    Os[1] = make_float4(ys[4], ys[5], ys[6], ys[7]);
    Os[2] = make_float4(ys[8], ys[9], ys[10], ys[11]);
    Os[3] = make_float4(ys[12], ys[13], ys[14], ys[15]);
    Oc[0] = make_float4(yc[0], yc[1], yc[2], yc[3]);
    Oc[1] = make_float4(yc[4], yc[5], yc[6], yc[7]);
    Oc[2] = make_float4(yc[8], yc[9], yc[10], yc[11]);
    Oc[3] = make_float4(yc[12], yc[13], yc[14], yc[15]);
}

// ---------------- host launcher ----------------

extern "C" void kernel_launch(void* const* d_in, const int* in_sizes, int n_in,
                              void* d_out, int out_size) {
    const float* x      = (const float*)d_in[0];
    const int*   ei     = (const int*)d_in[1];
    const float* W_in   = (const float*)d_in[2];
    const float* b_in   = (const float*)d_in[3];
    const float* Ws     = (const float*)d_in[4];
    const float* bs     = (const float*)d_in[5];
    const float* gammas = (const float*)d_in[6];
    const float* betas  = (const float*)d_in[7];
    const float* W_sin  = (const float*)d_in[8];
    const float* b_sin  = (const float*)d_in[9];
    const float* W_cos  = (const float*)d_in[10];
    const float* b_cos  = (const float*)d_in[11];
    float* out = (float*)d_out;

    int n = in_sizes[0] / 64;
    int E = in_sizes[1] / 2;
    int n4 = n * 4;

    int nbn  = (n + 255) / 256;
    int nbn4 = (n4 + 255) / 256;
    int nbe  = (E + 255) / 256;
    int nsb  = (n + 1023) / 1024;

    float* stats_base = nullptr;
    cudaGetSymbolAddress((void**)&stats_base, g_stats);

    // ---- graph prep ----
    k_init<<<nbn, 256>>>(ei, (E < 1024) ? E : 1024, n);
    k_count<<<nbe, 256>>>(ei, E);
    k_scan_block<<<nsb, 256>>>(n);
    k_scan_top<<<1, 256>>>(nsb);
    k_scan_final<<<nbn, 256>>>(n, E);
    k_fill<<<nbe, 256>>>(ei, E);

    // ---- input layer ----
    k_xw<<<nbn, 256>>>(x, W_in, n);
    k_agg_in<<<nbn4, 256>>>(b_in, n);

    // ---- 4 mid layers ----
    for (int l = 0; l < 4; l++) {
        k_agg_mid<<<nbn4, 256>>>(n);
        k_mm_stats<<<nbn, 256>>>(Ws + l * 256, bs + l * 16, stats_base + l * 32, n);
        k_bn_relu<<<nbn4, 256>>>(stats_base + l * 32, gammas + l * 16, betas + l * 16,
                                 (float)n, n4);
    }

    // ---- heads (share one aggregation) ----
    k_agg_mid<<<nbn4, 256>>>(n);
    k_final<<<nbn, 256>>>(W_sin, b_sin, W_cos, b_cos, out, n);
}

// round 3
// speedup vs baseline: 2.1040x; 1.1602x over previous
#include <cuda_runtime.h>
#include <cuda_fp16.h>

#define NMAX 200000
#define EMAX 6400000

// ---------------- static device scratch ----------------
static __device__ int   g_csr[EMAX];           // src only (features pre-scaled by dinv)
static __device__ int   g_cnt[NMAX];
static __device__ int   g_cursor[NMAX];
static __device__ int   g_excl[NMAX];
static __device__ int   g_rowstart[NMAX + 1];
static __device__ int   g_bsums[256];
static __device__ float g_dinv[NMAX];
static __device__ uint2 g_hA[NMAX * 4];        // pre-scaled fp16x4 quarter-rows (input layer)
static __device__ uint2 g_hB[NMAX * 4];        // pre-scaled fp16x4 quarter-rows (mid layers)
static __device__ float g_a[NMAX * 16];        // fp32 agg output
static __device__ float g_y[NMAX * 16];        // fp32 pre-BN
static __device__ float g_stats[4 * 32];       // per mid-layer [sum16, sumsq16]

// ---------------- helpers ----------------

// Per-block int64-vs-int32 layout detection: int64 entries (values < 2^31)
// have zero high words; int32 layout puts ~random node ids there.
__device__ __forceinline__ bool is64_layout(const int* __restrict__ ei, int E) {
    int m = (E < 1024) ? E : 1024;
    int any = 0;
    for (int k = threadIdx.x; k < m; k += blockDim.x) any |= ei[2 * k + 1];
    return __syncthreads_or(any) == 0;
}

// ---------------- prep ----------------

__global__ void k_count(const int* __restrict__ ei, int E) {
    bool is64 = is64_layout(ei, E);
    int e = blockIdx.x * blockDim.x + threadIdx.x;
    if (e >= E) return;
    int d = is64 ? ei[2 * E + 2 * e] : ei[E + e];
    atomicAdd(&g_cnt[d], 1);
}

// per-1024-region exclusive scan of g_cnt -> g_excl, region sums -> g_bsums
__global__ void k_scan_block(int n) {
    __shared__ int sh[256];
    int tid = threadIdx.x;
    int base = blockIdx.x * 1024 + tid * 4;
    int v0 = 0, v1 = 0, v2 = 0, v3 = 0;
    if (base + 0 < n) v0 = g_cnt[base + 0];
    if (base + 1 < n) v1 = g_cnt[base + 1];
    if (base + 2 < n) v2 = g_cnt[base + 2];
    if (base + 3 < n) v3 = g_cnt[base + 3];
    int tsum = v0 + v1 + v2 + v3;
    sh[tid] = tsum;
    __syncthreads();
    for (int off = 1; off < 256; off <<= 1) {
        int t = 0;
        if (tid >= off) t = sh[tid - off];
        __syncthreads();
        sh[tid] += t;
        __syncthreads();
    }
    int excl = sh[tid] - tsum;
    if (base + 0 < n) { g_excl[base + 0] = excl; excl += v0; }
    if (base + 1 < n) { g_excl[base + 1] = excl; excl += v1; }
    if (base + 2 < n) { g_excl[base + 2] = excl; excl += v2; }
    if (base + 3 < n) { g_excl[base + 3] = excl; }
    if (tid == 255) g_bsums[blockIdx.x] = sh[255];
}

// each region-block reduces bsums[0..region) itself (<=196 values), then
// finalizes rowstart/cursor/dinv for its 1024 nodes.
__global__ void k_scan_final(int n, int E) {
    __shared__ int ws[8];
    int tid = threadIdx.x;
    int r = blockIdx.x;
    int v = (tid < r) ? g_bsums[tid] : 0;
#pragma unroll
    for (int o = 16; o > 0; o >>= 1) v += __shfl_xor_sync(0xFFFFFFFFu, v, o);
    if ((tid & 31) == 0) ws[tid >> 5] = v;
    __syncthreads();
    int boff = ws[0] + ws[1] + ws[2] + ws[3] + ws[4] + ws[5] + ws[6] + ws[7];
    int base = r * 1024 + tid * 4;
#pragma unroll
    for (int k = 0; k < 4; k++) {
        int i = base + k;
        if (i < n) {
            int rs = g_excl[i] + boff;
            g_rowstart[i] = rs;
            g_cursor[i] = rs;
            g_dinv[i] = rsqrtf((float)g_cnt[i] + 1.0f);  // +1 self loop
        }
    }
    if (r == 0 && tid == 0) g_rowstart[n] = E;
}

__global__ void k_fill(const int* __restrict__ ei, int E) {
    bool is64 = is64_layout(ei, E);
    int e = blockIdx.x * blockDim.x + threadIdx.x;
    if (e >= E) return;
    int s, d;
    if (is64) { s = ei[2 * e]; d = ei[2 * E + 2 * e]; }
    else      { s = ei[e];     d = ei[E + e]; }
    int pos = atomicAdd(&g_cursor[d], 1);
    g_csr[pos] = s;
}

// ---------------- dense ----------------

// g_hA = fp16(dinv[row] * (x[n,64] @ W[64,16]))
__global__ void k_xw(const float* __restrict__ x, const float* __restrict__ W, int n) {
    __shared__ float sW[64 * 16];
    int tid = threadIdx.x;
    ((float4*)sW)[tid] = ((const float4*)W)[tid];
    __syncthreads();
    int row = blockIdx.x * 256 + tid;
    if (row >= n) return;
    const float4* xr = (const float4*)(x + (size_t)row * 64);
    float y[16];
#pragma unroll
    for (int j = 0; j < 16; j++) y[j] = 0.0f;
#pragma unroll
    for (int k4 = 0; k4 < 16; k4++) {
        float4 xv = xr[k4];
        int kb = k4 * 4;
#pragma unroll
        for (int j = 0; j < 16; j++) y[j] += xv.x * sW[(kb + 0) * 16 + j];
#pragma unroll
        for (int j = 0; j < 16; j++) y[j] += xv.y * sW[(kb + 1) * 16 + j];
#pragma unroll
        for (int j = 0; j < 16; j++) y[j] += xv.z * sW[(kb + 2) * 16 + j];
#pragma unroll
        for (int j = 0; j < 16; j++) y[j] += xv.w * sW[(kb + 3) * 16 + j];
    }
    float di = g_dinv[row];
    uint2* o = g_hA + (size_t)row * 4;
#pragma unroll
    for (int q = 0; q < 4; q++) {
        __half2 lo = __float22half2_rn(make_float2(y[q * 4 + 0] * di, y[q * 4 + 1] * di));
        __half2 hi = __float22half2_rn(make_float2(y[q * 4 + 2] * di, y[q * 4 + 3] * di));
        o[q] = make_uint2(*(unsigned*)&lo, *(unsigned*)&hi);
    }
}

// ---------------- aggregation core ----------------
// 4 lanes per node; lane q owns channels [4q,4q+4). Features are pre-scaled
// (hs = dinv*h), so: sum_raw = sum_{s in N(d)} hs[s] + hs[d]; caller scales by dinv[d].
// CSR = src only (4B/edge); shared across the 4-lane group via shuffles.
__device__ __forceinline__ float4 agg_core(const uint2* __restrict__ H, int i, int q,
                                           unsigned gmask) {
    uint2 self = H[(size_t)i * 4 + q];
    float2 slo = __half22float2(*(const __half2*)&self.x);
    float2 shi = __half22float2(*(const __half2*)&self.y);
    float4 acc = make_float4(slo.x, slo.y, shi.x, shi.y);
    int e = g_rowstart[i], e1 = g_rowstart[i + 1];
    for (; e + 8 <= e1; e += 8) {
        int sA = g_csr[e + q];
        int sB = g_csr[e + 4 + q];
#pragma unroll
        for (int r = 0; r < 4; r++) {
            int s0 = __shfl_sync(gmask, sA, r, 4);
            int s1 = __shfl_sync(gmask, sB, r, 4);
            uint2 v0 = H[(size_t)s0 * 4 + q];
            uint2 v1 = H[(size_t)s1 * 4 + q];
            float2 l0 = __half22float2(*(const __half2*)&v0.x);
            float2 h0 = __half22float2(*(const __half2*)&v0.y);
            float2 l1 = __half22float2(*(const __half2*)&v1.x);
            float2 h1 = __half22float2(*(const __half2*)&v1.y);
            acc.x += l0.x + l1.x; acc.y += l0.y + l1.y;
            acc.z += h0.x + h1.x; acc.w += h0.y + h1.y;
        }
    }
    if (e + 4 <= e1) {
        int sA = g_csr[e + q];
#pragma unroll
        for (int r = 0; r < 4; r++) {
            int s0 = __shfl_sync(gmask, sA, r, 4);
            uint2 v0 = H[(size_t)s0 * 4 + q];
            float2 l0 = __half22float2(*(const __half2*)&v0.x);
            float2 h0 = __half22float2(*(const __half2*)&v0.y);
            acc.x += l0.x; acc.y += l0.y; acc.z += h0.x; acc.w += h0.y;
        }
        e += 4;
    }
    for (; e < e1; e++) {
        int s = g_csr[e];
        uint2 v = H[(size_t)s * 4 + q];
        float2 lo = __half22float2(*(const __half2*)&v.x);
        float2 hi = __half22float2(*(const __half2*)&v.y);
        acc.x += lo.x; acc.y += lo.y; acc.z += hi.x; acc.w += hi.y;
    }
    return acc;
}

// input layer: h1 = dinv[d]*sum + b_in; store hB = fp16(dinv[d] * h1)
__global__ void k_agg_in(const float* __restrict__ b, int n) {
    int idx = blockIdx.x * blockDim.x + threadIdx.x;
    if (idx >= n * 4) return;
    int i = idx >> 2, q = idx & 3;
    unsigned gmask = 0xFu << ((threadIdx.x & 31) & ~3);
    float4 acc = agg_core(g_hA, i, q, gmask);
    float di = g_dinv[i];
    float4 bb = ((const float4*)b)[q];
    acc.x = (acc.x * di + bb.x) * di;
    acc.y = (acc.y * di + bb.y) * di;
    acc.z = (acc.z * di + bb.z) * di;
    acc.w = (acc.w * di + bb.w) * di;
    __half2 lo = __float22half2_rn(make_float2(acc.x, acc.y));
    __half2 hi = __float22half2_rn(make_float2(acc.z, acc.w));
    g_hB[(size_t)i * 4 + q] = make_uint2(*(unsigned*)&lo, *(unsigned*)&hi);
}

// mid/head layers: g_a = dinv[d] * sum (fp32)
__global__ void k_agg_mid(int n) {
    int idx = blockIdx.x * blockDim.x + threadIdx.x;
    if (idx >= n * 4) return;
    int i = idx >> 2, q = idx & 3;
    unsigned gmask = 0xFu << ((threadIdx.x & 31) & ~3);
    float4 acc = agg_core(g_hB, i, q, gmask);
    float di = g_dinv[i];
    acc.x *= di; acc.y *= di; acc.z *= di; acc.w *= di;
    ((float4*)g_a)[(size_t)i * 4 + q] = acc;
}

// g_y = g_a @ W + b; accumulate per-channel sum & sumsq into stats
__global__ void k_mm_stats(const float* __restrict__ W, const float* __restrict__ b,
                           float* __restrict__ stats, int n) {
    __shared__ float sW[256];
    __shared__ float sB[16];
    __shared__ float sSum[16], sSq[16];
    int tid = threadIdx.x;
    sW[tid] = W[tid];
    if (tid < 16) { sB[tid] = b[tid]; sSum[tid] = 0.0f; sSq[tid] = 0.0f; }
    __syncthreads();
    int row = blockIdx.x * 256 + tid;
    float y[16];
    if (row < n) {
        const float4* A4 = (const float4*)(g_a + (size_t)row * 16);
        float a[16];
        float4 t;
        t = A4[0]; a[0] = t.x; a[1] = t.y; a[2] = t.z; a[3] = t.w;
        t = A4[1]; a[4] = t.x; a[5] = t.y; a[6] = t.z; a[7] = t.w;
        t = A4[2]; a[8] = t.x; a[9] = t.y; a[10] = t.z; a[11] = t.w;
        t = A4[3]; a[12] = t.x; a[13] = t.y; a[14] = t.z; a[15] = t.w;
#pragma unroll
        for (int j = 0; j < 16; j++) y[j] = sB[j];
#pragma unroll
        for (int k = 0; k < 16; k++) {
            float av = a[k];
#pragma unroll
            for (int j = 0; j < 16; j++) y[j] += av * sW[k * 16 + j];
        }
        float4* O = (float4*)(g_y + (size_t)row * 16);
        O[0] = make_float4(y[0], y[1], y[2], y[3]);
        O[1] = make_float4(y[4], y[5], y[6], y[7]);
        O[2] = make_float4(y[8], y[9], y[10], y[11]);
        O[3] = make_float4(y[12], y[13], y[14], y[15]);
    } else {
#pragma unroll
        for (int j = 0; j < 16; j++) y[j] = 0.0f;
    }
#pragma unroll
    for (int j = 0; j < 16; j++) {
        float s = y[j];
        float qv = y[j] * y[j];
#pragma unroll
        for (int off = 16; off > 0; off >>= 1) {
            s  += __shfl_xor_sync(0xFFFFFFFFu, s, off);
            qv += __shfl_xor_sync(0xFFFFFFFFu, qv, off);
        }
        if ((tid & 31) == 0) {
            atomicAdd(&sSum[j], s);
            atomicAdd(&sSq[j], qv);
        }
    }
    __syncthreads();
    if (tid < 16) {
        atomicAdd(&stats[tid], sSum[tid]);
        atomicAdd(&stats[16 + tid], sSq[tid]);
    }
}

// hB = fp16(dinv * relu(gamma*(y-mean)*rsqrt(var+eps)+beta))
__global__ void k_bn_relu(const float* __restrict__ stats,
                          const float* __restrict__ gamma, const float* __restrict__ beta,
                          float fn, int n4) {
    __shared__ float sc[16], sh[16];
    int tid = threadIdx.x;
    if (tid < 16) {
        float m = stats[tid] / fn;
        float v = stats[16 + tid] / fn - m * m;
        v = fmaxf(v, 0.0f);
        float s = gamma[tid] * rsqrtf(v + 1e-5f);
        sc[tid] = s;
        sh[tid] = beta[tid] - m * s;
    }
    __syncthreads();
    int idx = blockIdx.x * blockDim.x + tid;
    if (idx >= n4) return;
    int q = idx & 3;
    float di = g_dinv[idx >> 2];
    float4 v = ((const float4*)g_y)[idx];
    v.x = di * fmaxf(v.x * sc[q * 4 + 0] + sh[q * 4 + 0], 0.0f);
    v.y = di * fmaxf(v.y * sc[q * 4 + 1] + sh[q * 4 + 1], 0.0f);
    v.z = di * fmaxf(v.z * sc[q * 4 + 2] + sh[q * 4 + 2], 0.0f);
    v.w = di * fmaxf(v.w * sc[q * 4 + 3] + sh[q * 4 + 3], 0.0f);
    __half2 lo = __float22half2_rn(make_float2(v.x, v.y));
    __half2 hi = __float22half2_rn(make_float2(v.z, v.w));
    g_hB[idx] = make_uint2(*(unsigned*)&lo, *(unsigned*)&hi);
}

// heads: out = [relu(g_a@Wsin+bsin); relu(g_a@Wcos+bcos)]
__global__ void k_final(const float* __restrict__ Wsin, const float* __restrict__ bsin,
                        const float* __restrict__ Wcos, const float* __restrict__ bcos,
                        float* __restrict__ out, int n) {
    __shared__ float sWs[256], sWc[256];
    __shared__ float sBs[16], sBc[16];
    int tid = threadIdx.x;
    sWs[tid] = Wsin[tid];
    sWc[tid] = Wcos[tid];
    if (tid < 16) { sBs[tid] = bsin[tid]; sBc[tid] = bcos[tid]; }
    __syncthreads();
    int row = blockIdx.x * 256 + tid;
    if (row >= n) return;
    const float4* A4 = (const float4*)(g_a + (size_t)row * 16);
    float a[16];
    float4 t;
    t = A4[0]; a[0] = t.x; a[1] = t.y; a[2] = t.z; a[3] = t.w;
    t = A4[1]; a[4] = t.x; a[5] = t.y; a[6] = t.z; a[7] = t.w;
    t = A4[2]; a[8] = t.x; a[9] = t.y; a[10] = t.z; a[11] = t.w;
    t = A4[3]; a[12] = t.x; a[13] = t.y; a[14] = t.z; a[15] = t.w;
    float ys[16], yc[16];
#pragma unroll
    for (int j = 0; j < 16; j++) { ys[j] = sBs[j]; yc[j] = sBc[j]; }
#pragma unroll
    for (int k = 0; k < 16; k++) {
        float av = a[k];
#pragma unroll
        for (int j = 0; j < 16; j++) {
            ys[j] += av * sWs[k * 16 + j];
            yc[j] += av * sWc[k * 16 + j];
        }
    }
#pragma unroll
    for (int j = 0; j < 16; j++) {
        ys[j] = fmaxf(ys[j], 0.0f);
        yc[j] = fmaxf(yc[j], 0.0f);
    }
    float4* Os = (float4*)(out + (size_t)row * 16);
    float4* Oc = (float4*)(out + (size_t)n * 16 + (size_t)row * 16);
    Os[0] = make_float4(ys[0], ys[1], ys[2], ys[3]);
    Os[1] = make_float4(ys[4], ys[5], ys[6], ys[7]);
    Os[2] = make_float4(ys[8], ys[9], ys[10], ys[11]);
    Os[3] = make_float4(ys[12], ys[13], ys[14], ys[15]);
    Oc[0] = make_float4(yc[0], yc[1], yc[2], yc[3]);
    Oc[1] = make_float4(yc[4], yc[5], yc[6], yc[7]);
    Oc[2] = make_float4(yc[8], yc[9], yc[10], yc[11]);
    Oc[3] = make_float4(yc[12], yc[13], yc[14], yc[15]);
}

// ---------------- host launcher ----------------

extern "C" void kernel_launch(void* const* d_in, const int* in_sizes, int n_in,
                              void* d_out, int out_size) {
    const float* x      = (const float*)d_in[0];
    const int*   ei     = (const int*)d_in[1];
    const float* W_in   = (const float*)d_in[2];
    const float* b_in   = (const float*)d_in[3];
    const float* Ws     = (const float*)d_in[4];
    const float* bs     = (const float*)d_in[5];
    const float* gammas = (const float*)d_in[6];
    const float* betas  = (const float*)d_in[7];
    const float* W_sin  = (const float*)d_in[8];
    const float* b_sin  = (const float*)d_in[9];
    const float* W_cos  = (const float*)d_in[10];
    const float* b_cos  = (const float*)d_in[11];
    float* out = (float*)d_out;

    int n = in_sizes[0] / 64;
    int E = in_sizes[1] / 2;
    int n4 = n * 4;

    int nbn  = (n + 255) / 256;
    int nbn4 = (n4 + 255) / 256;
    int nbe  = (E + 255) / 256;
    int nsb  = (n + 1023) / 1024;

    void* cnt_ptr = nullptr;  void* stats_ptr = nullptr;
    cudaGetSymbolAddress(&cnt_ptr, g_cnt);
    cudaGetSymbolAddress(&stats_ptr, g_stats);
    float* stats_base = (float*)stats_ptr;

    // ---- graph prep ----
    cudaMemsetAsync(cnt_ptr, 0, (size_t)n * sizeof(int));
    cudaMemsetAsync(stats_ptr, 0, 4 * 32 * sizeof(float));
    k_count<<<nbe, 256>>>(ei, E);
    k_scan_block<<<nsb, 256>>>(n);
    k_scan_final<<<nsb, 256>>>(n, E);
    k_fill<<<nbe, 256>>>(ei, E);

    // ---- input layer ----
    k_xw<<<nbn, 256>>>(x, W_in, n);
    k_agg_in<<<nbn4, 256>>>(b_in, n);

    // ---- 4 mid layers ----
    for (int l = 0; l < 4; l++) {
        k_agg_mid<<<nbn4, 256>>>(n);
        k_mm_stats<<<nbn, 256>>>(Ws + l * 256, bs + l * 16, stats_base + l * 32, n);
        k_bn_relu<<<nbn4, 256>>>(stats_base + l * 32, gammas + l * 16, betas + l * 16,
                                 (float)n, n4);
    }

    // ---- heads (share one aggregation) ----
    k_agg_mid<<<nbn4, 256>>>(n);
    k_final<<<nbn, 256>>>(W_sin, b_sin, W_cos, b_cos, out, n);
}

// round 4
// speedup vs baseline: 2.1753x; 1.0339x over previous
#include <cuda_runtime.h>
#include <cuda_fp16.h>

#define NMAX 200000
#define EMAX 6400000

// ---------------- static device scratch ----------------
static __device__ int   g_csr[EMAX];           // src only (features pre-scaled by dinv)
static __device__ int   g_cnt[NMAX];
static __device__ int   g_cursor[NMAX];
static __device__ int   g_excl[NMAX];
static __device__ int   g_rowstart[NMAX + 1];
static __device__ int   g_bsums[256];
static __device__ float g_dinv[NMAX];
static __device__ uint2 g_hA[NMAX * 4];        // pre-scaled fp16x4 quarter-rows (input layer)
static __device__ uint2 g_hB[NMAX * 4];        // pre-scaled fp16x4 quarter-rows (mid layers)
static __device__ float g_a[NMAX * 16];        // fp32 agg output
static __device__ float g_stats[4 * 32];       // per mid-layer [sum16, sumsq16] of y

// ---------------- helpers ----------------

// int64 entries (node ids < 2^31) have zero high words; int32 layout puts
// node ids there instead.
__device__ __forceinline__ bool is64_layout(const int* __restrict__ ei, int E) {
    int m = (E < 1024) ? E : 1024;
    int any = 0;
    for (int k = threadIdx.x; k < m; k += blockDim.x) any |= ei[2 * k + 1];
    return __syncthreads_or(any) == 0;
}

// ---------------- prep ----------------

// 4 edges per thread, int4 vector loads of dst ids.
__global__ void k_count(const int* __restrict__ ei, int E) {
    bool is64 = is64_layout(ei, E);
    int t = blockIdx.x * blockDim.x + threadIdx.x;
    int e0 = t * 4;
    bool vec = is64 ? ((E & 1) == 0) : ((E & 3) == 0);
    if (vec && e0 + 4 <= E) {
        int d0, d1, d2, d3;
        if (is64) {
            const int4* p = (const int4*)(ei + 2 * E);  // dst half as int64 pairs
            int4 a = p[2 * t], b = p[2 * t + 1];
            d0 = a.x; d1 = a.z; d2 = b.x; d3 = b.z;
        } else {
            int4 d = ((const int4*)(ei + E))[t];
            d0 = d.x; d1 = d.y; d2 = d.z; d3 = d.w;
        }
        atomicAdd(&g_cnt[d0], 1);
        atomicAdd(&g_cnt[d1], 1);
        atomicAdd(&g_cnt[d2], 1);
        atomicAdd(&g_cnt[d3], 1);
    } else {
        for (int e = e0; e < E && e < e0 + 4; e++) {
            int d = is64 ? ei[2 * E + 2 * e] : ei[E + e];
            atomicAdd(&g_cnt[d], 1);
        }
    }
}

// per-1024-region exclusive scan of g_cnt -> g_excl, region sums -> g_bsums
__global__ void k_scan_block(int n) {
    __shared__ int sh[256];
    int tid = threadIdx.x;
    int base = blockIdx.x * 1024 + tid * 4;
    int v0 = 0, v1 = 0, v2 = 0, v3 = 0;
    if (base + 0 < n) v0 = g_cnt[base + 0];
    if (base + 1 < n) v1 = g_cnt[base + 1];
    if (base + 2 < n) v2 = g_cnt[base + 2];
    if (base + 3 < n) v3 = g_cnt[base + 3];
    int tsum = v0 + v1 + v2 + v3;
    sh[tid] = tsum;
    __syncthreads();
    for (int off = 1; off < 256; off <<= 1) {
        int t = 0;
        if (tid >= off) t = sh[tid - off];
        __syncthreads();
        sh[tid] += t;
        __syncthreads();
    }
    int excl = sh[tid] - tsum;
    if (base + 0 < n) { g_excl[base + 0] = excl; excl += v0; }
    if (base + 1 < n) { g_excl[base + 1] = excl; excl += v1; }
    if (base + 2 < n) { g_excl[base + 2] = excl; excl += v2; }
    if (base + 3 < n) { g_excl[base + 3] = excl; }
    if (tid == 255) g_bsums[blockIdx.x] = sh[255];
}

// each region-block reduces bsums[0..region) itself, then finalizes
// rowstart/cursor/dinv for its 1024 nodes.
__global__ void k_scan_final(int n, int E) {
    __shared__ int ws[8];
    int tid = threadIdx.x;
    int r = blockIdx.x;
    int v = (tid < r) ? g_bsums[tid] : 0;
#pragma unroll
    for (int o = 16; o > 0; o >>= 1) v += __shfl_xor_sync(0xFFFFFFFFu, v, o);
    if ((tid & 31) == 0) ws[tid >> 5] = v;
    __syncthreads();
    int boff = ws[0] + ws[1] + ws[2] + ws[3] + ws[4] + ws[5] + ws[6] + ws[7];
    int base = r * 1024 + tid * 4;
#pragma unroll
    for (int k = 0; k < 4; k++) {
        int i = base + k;
        if (i < n) {
            int rs = g_excl[i] + boff;
            g_rowstart[i] = rs;
            g_cursor[i] = rs;
            g_dinv[i] = rsqrtf((float)g_cnt[i] + 1.0f);  // +1 self loop
        }
    }
    if (r == 0 && tid == 0) g_rowstart[n] = E;
}

// 4 edges per thread, int4 vector loads of both src and dst.
__global__ void k_fill(const int* __restrict__ ei, int E) {
    bool is64 = is64_layout(ei, E);
    int t = blockIdx.x * blockDim.x + threadIdx.x;
    int e0 = t * 4;
    bool vec = is64 ? ((E & 1) == 0) : ((E & 3) == 0);
    if (vec && e0 + 4 <= E) {
        int s0, s1, s2, s3, d0, d1, d2, d3;
        if (is64) {
            const int4* ps = (const int4*)ei;
            const int4* pd = (const int4*)(ei + 2 * E);
            int4 sa = ps[2 * t], sb = ps[2 * t + 1];
            int4 da = pd[2 * t], db = pd[2 * t + 1];
            s0 = sa.x; s1 = sa.z; s2 = sb.x; s3 = sb.z;
            d0 = da.x; d1 = da.z; d2 = db.x; d3 = db.z;
        } else {
            int4 s = ((const int4*)ei)[t];
            int4 d = ((const int4*)(ei + E))[t];
            s0 = s.x; s1 = s.y; s2 = s.z; s3 = s.w;
            d0 = d.x; d1 = d.y; d2 = d.z; d3 = d.w;
        }
        g_csr[atomicAdd(&g_cursor[d0], 1)] = s0;
        g_csr[atomicAdd(&g_cursor[d1], 1)] = s1;
        g_csr[atomicAdd(&g_cursor[d2], 1)] = s2;
        g_csr[atomicAdd(&g_cursor[d3], 1)] = s3;
    } else {
        for (int e = e0; e < E && e < e0 + 4; e++) {
            int s, d;
            if (is64) { s = ei[2 * e]; d = ei[2 * E + 2 * e]; }
            else      { s = ei[e];     d = ei[E + e]; }
            g_csr[atomicAdd(&g_cursor[d], 1)] = s;
        }
    }
}

// ---------------- dense ----------------

// g_hA = fp16(dinv[row] * (x[n,64] @ W[64,16]))
__global__ void k_xw(const float* __restrict__ x, const float* __restrict__ W, int n) {
    __shared__ float sW[64 * 16];
    int tid = threadIdx.x;
    ((float4*)sW)[tid] = ((const float4*)W)[tid];
    __syncthreads();
    int row = blockIdx.x * 256 + tid;
    if (row >= n) return;
    const float4* xr = (const float4*)(x + (size_t)row * 64);
    float y[16];
#pragma unroll
    for (int j = 0; j < 16; j++) y[j] = 0.0f;
#pragma unroll
    for (int k4 = 0; k4 < 16; k4++) {
        float4 xv = xr[k4];
        int kb = k4 * 4;
#pragma unroll
        for (int j = 0; j < 16; j++) y[j] += xv.x * sW[(kb + 0) * 16 + j];
#pragma unroll
        for (int j = 0; j < 16; j++) y[j] += xv.y * sW[(kb + 1) * 16 + j];
#pragma unroll
        for (int j = 0; j < 16; j++) y[j] += xv.z * sW[(kb + 2) * 16 + j];
#pragma unroll
        for (int j = 0; j < 16; j++) y[j] += xv.w * sW[(kb + 3) * 16 + j];
    }
    float di = g_dinv[row];
    uint2* o = g_hA + (size_t)row * 4;
#pragma unroll
    for (int q = 0; q < 4; q++) {
        __half2 lo = __float22half2_rn(make_float2(y[q * 4 + 0] * di, y[q * 4 + 1] * di));
        __half2 hi = __float22half2_rn(make_float2(y[q * 4 + 2] * di, y[q * 4 + 3] * di));
        o[q] = make_uint2(*(unsigned*)&lo, *(unsigned*)&hi);
    }
}

// ---------------- aggregation core ----------------
// 4 lanes per node; lane q owns channels [4q,4q+4). Features pre-scaled (hs=dinv*h):
// sum_raw = sum_{s in N(d)} hs[s] + hs[d]; caller scales by dinv[d].
__device__ __forceinline__ float4 agg_core(const uint2* __restrict__ H, int i, int q,
                                           unsigned gmask) {
    uint2 self = H[(size_t)i * 4 + q];
    float2 slo = __half22float2(*(const __half2*)&self.x);
    float2 shi = __half22float2(*(const __half2*)&self.y);
    float4 acc = make_float4(slo.x, slo.y, shi.x, shi.y);
    int e = g_rowstart[i], e1 = g_rowstart[i + 1];
    for (; e + 8 <= e1; e += 8) {
        int sA = g_csr[e + q];
        int sB = g_csr[e + 4 + q];
#pragma unroll
        for (int r = 0; r < 4; r++) {
            int s0 = __shfl_sync(gmask, sA, r, 4);
            int s1 = __shfl_sync(gmask, sB, r, 4);
            uint2 v0 = H[(size_t)s0 * 4 + q];
            uint2 v1 = H[(size_t)s1 * 4 + q];
            float2 l0 = __half22float2(*(const __half2*)&v0.x);
            float2 h0 = __half22float2(*(const __half2*)&v0.y);
            float2 l1 = __half22float2(*(const __half2*)&v1.x);
            float2 h1 = __half22float2(*(const __half2*)&v1.y);
            acc.x += l0.x + l1.x; acc.y += l0.y + l1.y;
            acc.z += h0.x + h1.x; acc.w += h0.y + h1.y;
        }
    }
    if (e + 4 <= e1) {
        int sA = g_csr[e + q];
#pragma unroll
        for (int r = 0; r < 4; r++) {
            int s0 = __shfl_sync(gmask, sA, r, 4);
            uint2 v0 = H[(size_t)s0 * 4 + q];
            float2 l0 = __half22float2(*(const __half2*)&v0.x);
            float2 h0 = __half22float2(*(const __half2*)&v0.y);
            acc.x += l0.x; acc.y += l0.y; acc.z += h0.x; acc.w += h0.y;
        }
        e += 4;
    }
    for (; e < e1; e++) {
        int s = g_csr[e];
        uint2 v = H[(size_t)s * 4 + q];
        float2 lo = __half22float2(*(const __half2*)&v.x);
        float2 hi = __half22float2(*(const __half2*)&v.y);
        acc.x += lo.x; acc.y += lo.y; acc.z += hi.x; acc.w += hi.y;
    }
    return acc;
}

// input layer: h1 = dinv[d]*sum + b_in; store hB = fp16(dinv[d] * h1)
__global__ void k_agg_in(const float* __restrict__ b, int n) {
    int idx = blockIdx.x * blockDim.x + threadIdx.x;
    if (idx >= n * 4) return;
    int i = idx >> 2, q = idx & 3;
    unsigned gmask = 0xFu << ((threadIdx.x & 31) & ~3);
    float4 acc = agg_core(g_hA, i, q, gmask);
    float di = g_dinv[i];
    float4 bb = ((const float4*)b)[q];
    acc.x = (acc.x * di + bb.x) * di;
    acc.y = (acc.y * di + bb.y) * di;
    acc.z = (acc.z * di + bb.z) * di;
    acc.w = (acc.w * di + bb.w) * di;
    __half2 lo = __float22half2_rn(make_float2(acc.x, acc.y));
    __half2 hi = __float22half2_rn(make_float2(acc.z, acc.w));
    g_hB[(size_t)i * 4 + q] = make_uint2(*(unsigned*)&lo, *(unsigned*)&hi);
}

// mid/head agg: g_a = dinv[d]*sum (fp32). If STATS, also accumulate per-channel
// sum/sumsq of y = a@W + b into stats (BN statistics, y itself not stored).
template <bool STATS>
__global__ void k_agg_mid_t(const float* __restrict__ W, const float* __restrict__ b,
                            float* __restrict__ stats, int n) {
    __shared__ float sW[256];
    __shared__ float sB[16];
    __shared__ float sSum[16], sSq[16];
    int tid = threadIdx.x;
    if (STATS) {
        sW[tid] = W[tid];
        if (tid < 16) { sB[tid] = b[tid]; sSum[tid] = 0.0f; sSq[tid] = 0.0f; }
        __syncthreads();
    }
    int idx = blockIdx.x * blockDim.x + tid;
    bool valid = idx < n * 4;
    int i = valid ? (idx >> 2) : 0;
    int q = idx & 3;
    int lane = tid & 31;
    unsigned gmask = 0xFu << (lane & ~3);
    float4 acc = agg_core(g_hB, i, q, gmask);
    float di = g_dinv[i];
    acc.x *= di; acc.y *= di; acc.z *= di; acc.w *= di;
    if (valid) ((float4*)g_a)[(size_t)i * 4 + q] = acc;
    if (STATS) {
        // assemble full 16-vector of node i across the 4-lane group
        float af[16];
        int base = lane & ~3;
#pragma unroll
        for (int r = 0; r < 4; r++) {
            af[r * 4 + 0] = __shfl_sync(0xFFFFFFFFu, acc.x, base + r);
            af[r * 4 + 1] = __shfl_sync(0xFFFFFFFFu, acc.y, base + r);
            af[r * 4 + 2] = __shfl_sync(0xFFFFFFFFu, acc.z, base + r);
            af[r * 4 + 3] = __shfl_sync(0xFFFFFFFFu, acc.w, base + r);
        }
        // this lane computes y for its 4 channels
        float s4[4], q4[4];
#pragma unroll
        for (int m = 0; m < 4; m++) {
            float y = sB[q * 4 + m];
#pragma unroll
            for (int k = 0; k < 16; k++) y += af[k] * sW[k * 16 + q * 4 + m];
            if (!valid) y = 0.0f;
            s4[m] = y;
            q4[m] = y * y;
        }
        // reduce across the 8 groups in the warp
#pragma unroll
        for (int off = 4; off < 32; off <<= 1) {
#pragma unroll
            for (int m = 0; m < 4; m++) {
                s4[m] += __shfl_xor_sync(0xFFFFFFFFu, s4[m], off);
                q4[m] += __shfl_xor_sync(0xFFFFFFFFu, q4[m], off);
            }
        }
        if (lane < 4) {
#pragma unroll
            for (int m = 0; m < 4; m++) {
                atomicAdd(&sSum[lane * 4 + m], s4[m]);
                atomicAdd(&sSq[lane * 4 + m], q4[m]);
            }
        }
        __syncthreads();
        if (tid < 16) {
            atomicAdd(&stats[tid], sSum[tid]);
            atomicAdd(&stats[16 + tid], sSq[tid]);
        }
    }
}

// hB = fp16(dinv * relu(BN(a@W+b)))  — recomputes y from a (no y buffer)
__global__ void k_bn_relu(const float* __restrict__ W, const float* __restrict__ b,
                          const float* __restrict__ stats,
                          const float* __restrict__ gamma, const float* __restrict__ beta,
                          float fn, int n) {
    __shared__ float sW[256];
    __shared__ float sc[16], sh2[16];
    int tid = threadIdx.x;
    sW[tid] = W[tid];
    if (tid < 16) {
        float m = stats[tid] / fn;
        float v = stats[16 + tid] / fn - m * m;
        v = fmaxf(v, 0.0f);
        float s = gamma[tid] * rsqrtf(v + 1e-5f);
        sc[tid] = s;
        sh2[tid] = beta[tid] - m * s + s * b[tid];  // fold bias into shift
    }
    __syncthreads();
    int row = blockIdx.x * 256 + tid;
    if (row >= n) return;
    const float4* A4 = (const float4*)(g_a + (size_t)row * 16);
    float a[16];
    float4 t;
    t = A4[0]; a[0] = t.x; a[1] = t.y; a[2] = t.z; a[3] = t.w;
    t = A4[1]; a[4] = t.x; a[5] = t.y; a[6] = t.z; a[7] = t.w;
    t = A4[2]; a[8] = t.x; a[9] = t.y; a[10] = t.z; a[11] = t.w;
    t = A4[3]; a[12] = t.x; a[13] = t.y; a[14] = t.z; a[15] = t.w;
    float y[16];
#pragma unroll
    for (int j = 0; j < 16; j++) y[j] = 0.0f;
#pragma unroll
    for (int k = 0; k < 16; k++) {
        float av = a[k];
#pragma unroll
        for (int j = 0; j < 16; j++) y[j] += av * sW[k * 16 + j];
    }
    float di = g_dinv[row];
    unsigned pk[8];
#pragma unroll
    for (int p = 0; p < 8; p++) {
        float v0 = di * fmaxf(y[2 * p + 0] * sc[2 * p + 0] + sh2[2 * p + 0], 0.0f);
        float v1 = di * fmaxf(y[2 * p + 1] * sc[2 * p + 1] + sh2[2 * p + 1], 0.0f);
        __half2 h = __float22half2_rn(make_float2(v0, v1));
        pk[p] = *(unsigned*)&h;
    }
    uint4* o = (uint4*)(g_hB + (size_t)row * 4);
    o[0] = make_uint4(pk[0], pk[1], pk[2], pk[3]);
    o[1] = make_uint4(pk[4], pk[5], pk[6], pk[7]);
}

// heads: out = [relu(g_a@Wsin+bsin); relu(g_a@Wcos+bcos)]
__global__ void k_final(const float* __restrict__ Wsin, const float* __restrict__ bsin,
                        const float* __restrict__ Wcos, const float* __restrict__ bcos,
                        float* __restrict__ out, int n) {
    __shared__ float sWs[256], sWc[256];
    __shared__ float sBs[16], sBc[16];
    int tid = threadIdx.x;
    sWs[tid] = Wsin[tid];
    sWc[tid] = Wcos[tid];
    if (tid < 16) { sBs[tid] = bsin[tid]; sBc[tid] = bcos[tid]; }
    __syncthreads();
    int row = blockIdx.x * 256 + tid;
    if (row >= n) return;
    const float4* A4 = (const float4*)(g_a + (size_t)row * 16);
    float a[16];
    float4 t;
    t = A4[0]; a[0] = t.x; a[1] = t.y; a[2] = t.z; a[3] = t.w;
    t = A4[1]; a[4] = t.x; a[5] = t.y; a[6] = t.z; a[7] = t.w;
    t = A4[2]; a[8] = t.x; a[9] = t.y; a[10] = t.z; a[11] = t.w;
    t = A4[3]; a[12] = t.x; a[13] = t.y; a[14] = t.z; a[15] = t.w;
    float ys[16], yc[16];
#pragma unroll
    for (int j = 0; j < 16; j++) { ys[j] = sBs[j]; yc[j] = sBc[j]; }
#pragma unroll
    for (int k = 0; k < 16; k++) {
        float av = a[k];
#pragma unroll
        for (int j = 0; j < 16; j++) {
            ys[j] += av * sWs[k * 16 + j];
            yc[j] += av * sWc[k * 16 + j];
        }
    }
#pragma unroll
    for (int j = 0; j < 16; j++) {
        ys[j] = fmaxf(ys[j], 0.0f);
        yc[j] = fmaxf(yc[j], 0.0f);
    }
    float4* Os = (float4*)(out + (size_t)row * 16);
    float4* Oc = (float4*)(out + (size_t)n * 16 + (size_t)row * 16);
    Os[0] = make_float4(ys[0], ys[1], ys[2], ys[3]);
    Os[1] = make_float4(ys[4], ys[5], ys[6], ys[7]);
    Os[2] = make_float4(ys[8], ys[9], ys[10], ys[11]);
    Os[3] = make_float4(ys[12], ys[13], ys[14], ys[15]);
    Oc[0] = make_float4(yc[0], yc[1], yc[2], yc[3]);
    Oc[1] = make_float4(yc[4], yc[5], yc[6], yc[7]);
    Oc[2] = make_float4(yc[8], yc[9], yc[10], yc[11]);
    Oc[3] = make_float4(yc[12], yc[13], yc[14], yc[15]);
}

// ---------------- host launcher ----------------

extern "C" void kernel_launch(void* const* d_in, const int* in_sizes, int n_in,
                              void* d_out, int out_size) {
    const float* x      = (const float*)d_in[0];
    const int*   ei     = (const int*)d_in[1];
    const float* W_in   = (const float*)d_in[2];
    const float* b_in   = (const float*)d_in[3];
    const float* Ws     = (const float*)d_in[4];
    const float* bs     = (const float*)d_in[5];
    const float* gammas = (const float*)d_in[6];
    const float* betas  = (const float*)d_in[7];
    const float* W_sin  = (const float*)d_in[8];
    const float* b_sin  = (const float*)d_in[9];
    const float* W_cos  = (const float*)d_in[10];
    const float* b_cos  = (const float*)d_in[11];
    float* out = (float*)d_out;

    int n = in_sizes[0] / 64;
    int E = in_sizes[1] / 2;

    int nbn  = (n + 255) / 256;
    int nbn4 = (n * 4 + 255) / 256;
    int nbe4 = ((E + 3) / 4 + 255) / 256;
    int nsb  = (n + 1023) / 1024;

    void* cnt_ptr = nullptr;  void* stats_ptr = nullptr;
    cudaGetSymbolAddress(&cnt_ptr, g_cnt);
    cudaGetSymbolAddress(&stats_ptr, g_stats);
    float* stats_base = (float*)stats_ptr;

    // ---- graph prep ----
    cudaMemsetAsync(cnt_ptr, 0, (size_t)n * sizeof(int));
    cudaMemsetAsync(stats_ptr, 0, 4 * 32 * sizeof(float));
    k_count<<<nbe4, 256>>>(ei, E);
    k_scan_block<<<nsb, 256>>>(n);
    k_scan_final<<<nsb, 256>>>(n, E);
    k_fill<<<nbe4, 256>>>(ei, E);

    // ---- input layer ----
    k_xw<<<nbn, 256>>>(x, W_in, n);
    k_agg_in<<<nbn4, 256>>>(b_in, n);

    // ---- 4 mid layers: agg(+stats) then fused matmul+BN+relu ----
    for (int l = 0; l < 4; l++) {
        k_agg_mid_t<true><<<nbn4, 256>>>(Ws + l * 256, bs + l * 16,
                                         stats_base + l * 32, n);
        k_bn_relu<<<nbn, 256>>>(Ws + l * 256, bs + l * 16, stats_base + l * 32,
                                gammas + l * 16, betas + l * 16, (float)n, n);
    }

    // ---- heads (share one aggregation, no stats) ----
    k_agg_mid_t<false><<<nbn4, 256>>>(nullptr, nullptr, nullptr, n);
    k_final<<<nbn, 256>>>(W_sin, b_sin, W_cos, b_cos, out, n);
}